// round 14
// baseline (speedup 1.0000x reference)
#include <cuda_runtime.h>
#include <cuda_fp16.h>
#include <cstdint>

#define OUT_F  4096
#define IN_F   4096
#define TOKENS 8192

// Device scratch: dequantized W (32 MB).
__device__ __align__(256) __half g_W[(size_t)OUT_F * IN_F];

// ---------------------------------------------------------------------------
// Kernel 1: NF4-style double dequant. 4 packed bytes -> 8 halves per thread.
// ---------------------------------------------------------------------------
__global__ void dequant_kernel(const int* __restrict__ qw,
                               const int* __restrict__ absmax,
                               const float* __restrict__ code,
                               const float* __restrict__ offset,
                               const float* __restrict__ s2a,
                               const float* __restrict__ s2c) {
    int j4 = blockIdx.x * blockDim.x + threadIdx.x;
    int j  = j4 << 2;
    int4 q = reinterpret_cast<const int4*>(qw)[j4];
    int b1 = j >> 5;
    int b2 = j >> 7;
    float scale = ((float)absmax[b1] / code[b1]) * (s2a[b2] / s2c[b2]);
    float off   = offset[b1];
    int v[4] = {q.x, q.y, q.z, q.w};
    __half out[8];
#pragma unroll
    for (int t = 0; t < 4; ++t) {
        out[2 * t]     = __float2half(((float)(v[t] & 15)        - off) * scale);
        out[2 * t + 1] = __float2half(((float)((v[t] >> 4) & 15) - off) * scale);
    }
    reinterpret_cast<uint4*>(g_W)[j4] = *reinterpret_cast<uint4*>(out);
}

// ---------------------------------------------------------------------------
// Kernel 2: fused fp32->fp16 convert + fp16 GEMM  C = X * W^T, fp32 output.
// BM=128, BN=256, BK=64; 16 warps in 4x4, warp tile 32x64 (512 threads).
// A loaded as fp32 via LDG (converted in-kernel), B via cp.async.
// 3-stage pipeline, SW128 swizzled smem.
// ---------------------------------------------------------------------------
#define BM 128
#define BN 256
#define BK 64
#define STAGES 3
#define NTHREADS 512
#define A_BYTES (BM * BK * 2)            // 16 KB (fp16 in smem)
#define B_BYTES (BN * BK * 2)            // 32 KB
#define STAGE_BYTES (A_BYTES + B_BYTES)  // 48 KB

__device__ __forceinline__ uint32_t sw128(uint32_t b) {
    return b ^ ((b >> 3) & 0x70);
}

__global__ __launch_bounds__(NTHREADS, 1)
void gemm_kernel(const float* __restrict__ X, float* __restrict__ C) {
    extern __shared__ char smem[];
    const int tid    = threadIdx.x;
    const int lane   = tid & 31;
    const int wid    = tid >> 5;
    const int warp_m = wid >> 2;   // 0..3  -> 32-row slab
    const int warp_n = wid & 3;    // 0..3  -> 64-col slab
    const int bm = blockIdx.y, bn = blockIdx.x;

    const __half* Bblk = g_W + (size_t)bn * BN * IN_F;

    uint32_t s_base = (uint32_t)__cvta_generic_to_shared(smem);

    // --- A loader (fp32 -> fp16): thread t handles row t>>2, 16-float chunk t&3
    const int a_ld_row = tid >> 2;    // 0..127
    const int a_ld_q   = tid & 3;     // 0..3 (16 floats = 64B each)
    const float* Axrow = X + (size_t)(bm * BM + a_ld_row) * IN_F + a_ld_q * 16;
    const uint32_t a_off0 = sw128((uint32_t)(a_ld_row * 128 + a_ld_q * 32));
    const uint32_t a_off1 = sw128((uint32_t)(a_ld_row * 128 + a_ld_q * 32 + 16));

    // --- B loader: thread t handles row t>>3 (+64 strides), 16B chunk t&7
    const int b_ld_row = tid >> 3;    // 0..63
    const int b_ld_ch  = tid & 7;
    const uint32_t b_soff0 = (uint32_t)(b_ld_row * 128 + b_ld_ch * 16);

    const int a_row = warp_m * 32 + (lane & 15);
    const int b_row = warp_n * 64 + (lane & 15);
    const int colh8 = ((lane >> 4) & 1) * 8;

    float acc[2][8][4];
#pragma unroll
    for (int mi = 0; mi < 2; ++mi)
#pragma unroll
        for (int ni = 0; ni < 8; ++ni)
#pragma unroll
            for (int t = 0; t < 4; ++t) acc[mi][ni][t] = 0.f;

    auto ldgA = [&](int kt, float4* buf) {
        const float4* p = reinterpret_cast<const float4*>(Axrow + kt * BK);
        buf[0] = p[0]; buf[1] = p[1]; buf[2] = p[2]; buf[3] = p[3];
    };
    auto stsA = [&](int stage, const float4* buf) {
        uint32_t base = s_base + stage * STAGE_BYTES;
        uint32_t w[8];
#pragma unroll
        for (int i = 0; i < 4; ++i) {
            __half2 lo = __floats2half2_rn(buf[i].x, buf[i].y);
            __half2 hi = __floats2half2_rn(buf[i].z, buf[i].w);
            w[2 * i]     = *reinterpret_cast<uint32_t*>(&lo);
            w[2 * i + 1] = *reinterpret_cast<uint32_t*>(&hi);
        }
        asm volatile("st.shared.v4.b32 [%0], {%1,%2,%3,%4};"
                     :: "r"(base + a_off0), "r"(w[0]), "r"(w[1]), "r"(w[2]), "r"(w[3]));
        asm volatile("st.shared.v4.b32 [%0], {%1,%2,%3,%4};"
                     :: "r"(base + a_off1), "r"(w[4]), "r"(w[5]), "r"(w[6]), "r"(w[7]));
    };
    auto loadB = [&](int stage, int kt) {
        uint32_t b_s = s_base + stage * STAGE_BYTES + A_BYTES;
        int k0 = kt * BK;
#pragma unroll
        for (int r = 0; r < 4; ++r) {   // 256 rows in 4 passes of 64
            uint32_t soff = sw128(b_soff0 + (uint32_t)r * 64 * 128);
            const void* gb = Bblk + (size_t)(b_ld_row + r * 64) * IN_F + k0 + b_ld_ch * 8;
            asm volatile("cp.async.cg.shared.global [%0], [%1], 16;\n"
                         :: "r"(b_s + soff), "l"(gb));
        }
    };

    const int k_tiles = IN_F / BK;   // 64

    // prologue: stages 0,1
    {
        float4 ab[4];
        ldgA(0, ab);
        loadB(0, 0);
        asm volatile("cp.async.commit_group;\n");
        stsA(0, ab);
        ldgA(1, ab);
        loadB(1, 1);
        asm volatile("cp.async.commit_group;\n");
        stsA(1, ab);
    }

    for (int kt = 0; kt < k_tiles; ++kt) {
        asm volatile("cp.async.wait_group %0;\n" :: "n"(STAGES - 2));
        __syncthreads();

        int nkt = kt + STAGES - 1;
        bool pf = nkt < k_tiles;
        float4 abuf[4];
        if (pf) {
            ldgA(nkt, abuf);
            loadB(nkt % STAGES, nkt);
        }
        asm volatile("cp.async.commit_group;\n");

        uint32_t a_s = s_base + (kt % STAGES) * STAGE_BYTES;
        uint32_t b_s = a_s + A_BYTES;

#pragma unroll
        for (int ks = 0; ks < BK / 16; ++ks) {
            uint32_t a_frag[2][4];
            uint32_t b_frag[8][2];
            int colh = ks * 16 + colh8;
#pragma unroll
            for (int mi = 0; mi < 2; ++mi) {
                int row = a_row + mi * 16;
                uint32_t addr = a_s + sw128((uint32_t)(row * 128 + colh * 2));
                asm volatile(
                    "ldmatrix.sync.aligned.m8n8.x4.shared.b16 {%0,%1,%2,%3}, [%4];\n"
                    : "=r"(a_frag[mi][0]), "=r"(a_frag[mi][1]),
                      "=r"(a_frag[mi][2]), "=r"(a_frag[mi][3])
                    : "r"(addr));
            }
#pragma unroll
            for (int ng = 0; ng < 4; ++ng) {
                int row = b_row + ng * 16;
                uint32_t addr = b_s + sw128((uint32_t)(row * 128 + colh * 2));
                uint32_t r0, r1, r2, r3;
                asm volatile(
                    "ldmatrix.sync.aligned.m8n8.x4.shared.b16 {%0,%1,%2,%3}, [%4];\n"
                    : "=r"(r0), "=r"(r1), "=r"(r2), "=r"(r3)
                    : "r"(addr));
                b_frag[2 * ng][0]     = r0;
                b_frag[2 * ng + 1][0] = r1;
                b_frag[2 * ng][1]     = r2;
                b_frag[2 * ng + 1][1] = r3;
            }
#pragma unroll
            for (int mi = 0; mi < 2; ++mi)
#pragma unroll
                for (int ni = 0; ni < 8; ++ni) {
                    asm volatile(
                        "mma.sync.aligned.m16n8k16.row.col.f32.f16.f16.f32 "
                        "{%0,%1,%2,%3}, {%4,%5,%6,%7}, {%8,%9}, {%0,%1,%2,%3};\n"
                        : "+f"(acc[mi][ni][0]), "+f"(acc[mi][ni][1]),
                          "+f"(acc[mi][ni][2]), "+f"(acc[mi][ni][3])
                        : "r"(a_frag[mi][0]), "r"(a_frag[mi][1]),
                          "r"(a_frag[mi][2]), "r"(a_frag[mi][3]),
                          "r"(b_frag[ni][0]), "r"(b_frag[ni][1]));
                }
        }

        // convert+store prefetched A after mma (LDG latency hidden by mma work;
        // STS drained by the __syncthreads of iteration kt+1)
        if (pf) stsA(nkt % STAGES, abuf);
    }

    // epilogue: fp32 accumulators -> float32 output
    float* Cblk = C + (size_t)bm * BM * OUT_F + bn * BN;
#pragma unroll
    for (int mi = 0; mi < 2; ++mi)
#pragma unroll
        for (int ni = 0; ni < 8; ++ni) {
            int r0 = warp_m * 32 + mi * 16 + (lane >> 2);
            int cc = warp_n * 64 + ni * 8 + (lane & 3) * 2;
            float2 v0 = make_float2(acc[mi][ni][0], acc[mi][ni][1]);
            float2 v1 = make_float2(acc[mi][ni][2], acc[mi][ni][3]);
            *reinterpret_cast<float2*>(Cblk + (size_t)r0 * OUT_F + cc)       = v0;
            *reinterpret_cast<float2*>(Cblk + (size_t)(r0 + 8) * OUT_F + cc) = v1;
        }
}

// ---------------------------------------------------------------------------
extern "C" void kernel_launch(void* const* d_in, const int* in_sizes, int n_in,
                              void* d_out, int out_size) {
    const float* x       = (const float*)d_in[0];
    const int*   qw      = (const int*)d_in[1];
    const int*   absmax  = (const int*)d_in[2];
    const float* code    = (const float*)d_in[3];
    const float* offset  = (const float*)d_in[4];
    const float* s2a     = (const float*)d_in[5];
    const float* s2c     = (const float*)d_in[6];
    float* out = (float*)d_out;

    const int P4 = (OUT_F * IN_F / 2) / 4;
    dequant_kernel<<<P4 / 256, 256>>>(qw, absmax, code, offset, s2a, s2c);

    const int smem_bytes = STAGES * STAGE_BYTES;   // 144 KB
    cudaFuncSetAttribute(gemm_kernel,
                         cudaFuncAttributeMaxDynamicSharedMemorySize, smem_bytes);
    dim3 grid(OUT_F / BN, TOKENS / BM);            // (16, 64)
    gemm_kernel<<<grid, NTHREADS, smem_bytes>>>(x, out);
}

// round 16
// speedup vs baseline: 1.2822x; 1.2822x over previous
#include <cuda_runtime.h>
#include <cuda_fp16.h>
#include <cstdint>

#define OUT_F  4096
#define IN_F   4096
#define TOKENS 8192

// Device scratch: dequantized W (32 MB) + fp16 x (64 MB).
__device__ __align__(256) __half g_W[(size_t)OUT_F * IN_F];
__device__ __align__(256) __half g_A[(size_t)TOKENS * IN_F];

// ---------------------------------------------------------------------------
// Kernel 0: convert fp32 activations -> fp16 (8 elems / thread)
// ---------------------------------------------------------------------------
__global__ void convert_x_kernel(const float* __restrict__ x) {
    size_t i = ((size_t)blockIdx.x * blockDim.x + threadIdx.x) * 8;
    float4 f0 = *reinterpret_cast<const float4*>(x + i);
    float4 f1 = *reinterpret_cast<const float4*>(x + i + 4);
    __half h[8];
    h[0] = __float2half(f0.x); h[1] = __float2half(f0.y);
    h[2] = __float2half(f0.z); h[3] = __float2half(f0.w);
    h[4] = __float2half(f1.x); h[5] = __float2half(f1.y);
    h[6] = __float2half(f1.z); h[7] = __float2half(f1.w);
    *reinterpret_cast<uint4*>(g_A + i) = *reinterpret_cast<uint4*>(h);
}

// ---------------------------------------------------------------------------
// Kernel 1: NF4-style double dequant. 4 packed bytes -> 8 halves per thread.
// ---------------------------------------------------------------------------
__global__ void dequant_kernel(const int* __restrict__ qw,
                               const int* __restrict__ absmax,
                               const float* __restrict__ code,
                               const float* __restrict__ offset,
                               const float* __restrict__ s2a,
                               const float* __restrict__ s2c) {
    int j4 = blockIdx.x * blockDim.x + threadIdx.x;
    int j  = j4 << 2;
    int4 q = reinterpret_cast<const int4*>(qw)[j4];
    int b1 = j >> 5;
    int b2 = j >> 7;
    float scale = ((float)absmax[b1] / code[b1]) * (s2a[b2] / s2c[b2]);
    float off   = offset[b1];
    int v[4] = {q.x, q.y, q.z, q.w};
    __half out[8];
#pragma unroll
    for (int t = 0; t < 4; ++t) {
        out[2 * t]     = __float2half(((float)(v[t] & 15)        - off) * scale);
        out[2 * t + 1] = __float2half(((float)((v[t] >> 4) & 15) - off) * scale);
    }
    reinterpret_cast<uint4*>(g_W)[j4] = *reinterpret_cast<uint4*>(out);
}

// ---------------------------------------------------------------------------
// Kernel 2: fp16 GEMM  C[M,N] = A[M,K] * W^T, fp32 output.
// BM=128, BN=256, BK=64; 8 warps in 2x4, warp tile 64x64 (256 threads).
// 3-stage cp.async pipeline + CROSS-ITERATION fragment software pipeline:
// ldmatrix for k-slice s+1 (even across stage boundaries) issues before the
// mma chain of slice s, so LDS latency is always hidden under ~256cyc of mma.
// ---------------------------------------------------------------------------
#define BM 128
#define BN 256
#define BK 64
#define STAGES 3
#define NTHREADS 256
#define A_BYTES (BM * BK * 2)            // 16 KB
#define B_BYTES (BN * BK * 2)            // 32 KB
#define STAGE_BYTES (A_BYTES + B_BYTES)  // 48 KB

__device__ __forceinline__ uint32_t sw128(uint32_t b) {
    return b ^ ((b >> 3) & 0x70);
}

__global__ __launch_bounds__(NTHREADS, 1)
void gemm_kernel(float* __restrict__ C) {
    extern __shared__ char smem[];
    const int tid    = threadIdx.x;
    const int lane   = tid & 31;
    const int wid    = tid >> 5;
    const int warp_m = wid >> 2;   // 0..1  -> 64-row slab
    const int warp_n = wid & 3;    // 0..3  -> 64-col slab
    const int bm = blockIdx.y, bn = blockIdx.x;

    const __half* Ablk = g_A + (size_t)bm * BM * IN_F;
    const __half* Bblk = g_W + (size_t)bn * BN * IN_F;

    uint32_t s_base = (uint32_t)__cvta_generic_to_shared(smem);

    const int ldrow   = tid >> 3;  // 0..31
    const int ldchunk = tid & 7;   // 16B chunk within 128B row

    const int a_row = warp_m * 64 + (lane & 15);
    const int b_row = warp_n * 64 + (lane & 15);
    const int colh8 = ((lane >> 4) & 1) * 8;   // 8-half sub-column

    float acc[4][8][4];
#pragma unroll
    for (int mi = 0; mi < 4; ++mi)
#pragma unroll
        for (int ni = 0; ni < 8; ++ni)
#pragma unroll
            for (int t = 0; t < 4; ++t) acc[mi][ni][t] = 0.f;

    auto load_stage = [&](int stage, int kt) {
        uint32_t a_s = s_base + stage * STAGE_BYTES;
        uint32_t b_s = a_s + A_BYTES;
        int k0 = kt * BK;
        uint32_t soff0 = (uint32_t)(ldrow * 128 + ldchunk * 16);
#pragma unroll
        for (int r = 0; r < 4; ++r) {   // A: 128 rows in 4 passes of 32
            uint32_t soff = sw128(soff0 + (uint32_t)r * 32 * 128);
            const void* ga = Ablk + (size_t)(ldrow + r * 32) * IN_F + k0 + ldchunk * 8;
            asm volatile("cp.async.cg.shared.global [%0], [%1], 16;\n"
                         :: "r"(a_s + soff), "l"(ga));
        }
#pragma unroll
        for (int r = 0; r < 8; ++r) {   // B: 256 rows in 8 passes of 32
            uint32_t soff = sw128(soff0 + (uint32_t)r * 32 * 128);
            const void* gb = Bblk + (size_t)(ldrow + r * 32) * IN_F + k0 + ldchunk * 8;
            asm volatile("cp.async.cg.shared.global [%0], [%1], 16;\n"
                         :: "r"(b_s + soff), "l"(gb));
        }
    };

    // double-buffered fragment sets
    uint32_t aF[2][4][4];
    uint32_t bF[2][8][2];

    auto load_frags = [&](uint32_t a_s, uint32_t b_s, int ks, int buf) {
        int colh = ks * 16 + colh8;
#pragma unroll
        for (int mi = 0; mi < 4; ++mi) {
            int row = a_row + mi * 16;
            uint32_t addr = a_s + sw128((uint32_t)(row * 128 + colh * 2));
            asm volatile(
                "ldmatrix.sync.aligned.m8n8.x4.shared.b16 {%0,%1,%2,%3}, [%4];\n"
                : "=r"(aF[buf][mi][0]), "=r"(aF[buf][mi][1]),
                  "=r"(aF[buf][mi][2]), "=r"(aF[buf][mi][3])
                : "r"(addr));
        }
#pragma unroll
        for (int ng = 0; ng < 4; ++ng) {
            int row = b_row + ng * 16;
            uint32_t addr = b_s + sw128((uint32_t)(row * 128 + colh * 2));
            uint32_t r0, r1, r2, r3;
            asm volatile(
                "ldmatrix.sync.aligned.m8n8.x4.shared.b16 {%0,%1,%2,%3}, [%4];\n"
                : "=r"(r0), "=r"(r1), "=r"(r2), "=r"(r3)
                : "r"(addr));
            bF[buf][2 * ng][0]     = r0;
            bF[buf][2 * ng + 1][0] = r1;
            bF[buf][2 * ng][1]     = r2;
            bF[buf][2 * ng + 1][1] = r3;
        }
    };

    const int k_tiles = IN_F / BK;   // 64

    // prologue: stages 0,1 in flight; frags for (kt=0, ks=0) in buf 0
    load_stage(0, 0);
    asm volatile("cp.async.commit_group;\n");
    load_stage(1, 1);
    asm volatile("cp.async.commit_group;\n");
    asm volatile("cp.async.wait_group 1;\n");
    __syncthreads();
    load_frags(s_base, s_base + A_BYTES, 0, 0);

    for (int kt = 0; kt < k_tiles; ++kt) {
        int nkt = kt + 2;
        if (nkt < k_tiles) load_stage(nkt % STAGES, nkt);
        asm volatile("cp.async.commit_group;\n");
        asm volatile("cp.async.wait_group 1;\n");   // stage kt+1 arrived
        __syncthreads();                            // ..and visible to all

        uint32_t a_s = s_base + (kt % STAGES) * STAGE_BYTES;
        uint32_t b_s = a_s + A_BYTES;

#pragma unroll
        for (int ks = 0; ks < BK / 16; ++ks) {
            const int cur = ks & 1;
            // prefetch next k-slice's fragments BEFORE this slice's mma chain
            if (ks < BK / 16 - 1) {
                load_frags(a_s, b_s, ks + 1, cur ^ 1);
            } else if (kt < k_tiles - 1) {
                uint32_t na = s_base + ((kt + 1) % STAGES) * STAGE_BYTES;
                load_frags(na, na + A_BYTES, 0, cur ^ 1);
            }
#pragma unroll
            for (int mi = 0; mi < 4; ++mi)
#pragma unroll
                for (int ni = 0; ni < 8; ++ni) {
                    asm volatile(
                        "mma.sync.aligned.m16n8k16.row.col.f32.f16.f16.f32 "
                        "{%0,%1,%2,%3}, {%4,%5,%6,%7}, {%8,%9}, {%0,%1,%2,%3};\n"
                        : "+f"(acc[mi][ni][0]), "+f"(acc[mi][ni][1]),
                          "+f"(acc[mi][ni][2]), "+f"(acc[mi][ni][3])
                        : "r"(aF[cur][mi][0]), "r"(aF[cur][mi][1]),
                          "r"(aF[cur][mi][2]), "r"(aF[cur][mi][3]),
                          "r"(bF[cur][ni][0]), "r"(bF[cur][ni][1]));
                }
        }
    }

    // epilogue: fp32 accumulators -> float32 output
    float* Cblk = C + (size_t)bm * BM * OUT_F + bn * BN;
#pragma unroll
    for (int mi = 0; mi < 4; ++mi)
#pragma unroll
        for (int ni = 0; ni < 8; ++ni) {
            int r0 = warp_m * 64 + mi * 16 + (lane >> 2);
            int cc = warp_n * 64 + ni * 8 + (lane & 3) * 2;
            float2 v0 = make_float2(acc[mi][ni][0], acc[mi][ni][1]);
            float2 v1 = make_float2(acc[mi][ni][2], acc[mi][ni][3]);
            *reinterpret_cast<float2*>(Cblk + (size_t)r0 * OUT_F + cc)       = v0;
            *reinterpret_cast<float2*>(Cblk + (size_t)(r0 + 8) * OUT_F + cc) = v1;
        }
}

// ---------------------------------------------------------------------------
extern "C" void kernel_launch(void* const* d_in, const int* in_sizes, int n_in,
                              void* d_out, int out_size) {
    const float* x       = (const float*)d_in[0];
    const int*   qw      = (const int*)d_in[1];
    const int*   absmax  = (const int*)d_in[2];
    const float* code    = (const float*)d_in[3];
    const float* offset  = (const float*)d_in[4];
    const float* s2a     = (const float*)d_in[5];
    const float* s2c     = (const float*)d_in[6];
    float* out = (float*)d_out;

    const size_t NA = (size_t)TOKENS * IN_F;
    convert_x_kernel<<<(int)(NA / 8 / 256), 256>>>(x);

    const int P4 = (OUT_F * IN_F / 2) / 4;
    dequant_kernel<<<P4 / 256, 256>>>(qw, absmax, code, offset, s2a, s2c);

    const int smem_bytes = STAGES * STAGE_BYTES;   // 144 KB
    cudaFuncSetAttribute(gemm_kernel,
                         cudaFuncAttributeMaxDynamicSharedMemorySize, smem_bytes);
    dim3 grid(OUT_F / BN, TOKENS / BM);            // (16, 64)
    gemm_kernel<<<grid, NTHREADS, smem_bytes>>>(out);
}